// round 16
// baseline (speedup 1.0000x reference)
#include <cuda_runtime.h>
#include <cuda_fp16.h>
#include <cstdint>
#include <cstddef>
#include <math.h>

// Problem constants
#define BB   2
#define TT   2048
#define HH   2048
#define NH   16
#define NKV  8
#define HD   128
#define MM   (BB*TT)            // 4096 rows

// ---------------- scratch (static device globals; no allocation) -------------
__device__ float g_qkvraw[(size_t)MM * 4096];      // [b*T+t, {Q|K|V}]
__device__ __half g_qt[(size_t)BB * NH * TT * HD]; // [b,h,t,d] fp16
__device__ __half g_kt[(size_t)BB * NKV * TT * HD];
__device__ __half g_vt[(size_t)BB * NKV * TT * HD];
__device__ __half g_xh[(size_t)MM * HH];           // x fp16
__device__ __half g_wqkv[(size_t)4096 * 2048];     // [N=4096, K=2048] fp16 (Q|K|V rows)
__device__ __half g_wo[(size_t)2048 * 2048];       // Wo^T [N,K] fp16
__device__ __half g_ctx[(size_t)MM * HH];          // [b*T+t, h*HD+d] fp16
__device__ float g_cos[TT * 64];
__device__ float g_sin[TT * 64];

// ---------------- helpers ----------------------------------------------------
__device__ __forceinline__ uint32_t smem_u32(const void* p) {
    uint32_t a;
    asm("{ .reg .u64 t; cvta.to.shared.u64 t, %1; cvt.u32.u64 %0, t; }" : "=r"(a) : "l"(p));
    return a;
}

__device__ __forceinline__ void mma_f16(float c[4], const uint32_t a[4],
                                        uint32_t b0, uint32_t b1) {
    asm volatile(
        "mma.sync.aligned.m16n8k16.row.col.f32.f16.f16.f32 "
        "{%0,%1,%2,%3}, {%4,%5,%6,%7}, {%8,%9}, {%0,%1,%2,%3};\n"
        : "+f"(c[0]), "+f"(c[1]), "+f"(c[2]), "+f"(c[3])
        : "r"(a[0]), "r"(a[1]), "r"(a[2]), "r"(a[3]), "r"(b0), "r"(b1));
}

__device__ __forceinline__ float ex2(float x) {
    float r;
    asm("ex2.approx.ftz.f32 %0, %1;" : "=f"(r) : "f"(x));
    return r;
}

#define LDSM_X4(R0,R1,R2,R3,ADDR)                                              \
    asm volatile("ldmatrix.sync.aligned.m8n8.x4.shared.b16 {%0,%1,%2,%3}, [%4];" \
        : "=r"(R0), "=r"(R1), "=r"(R2), "=r"(R3) : "r"(ADDR))
#define LDSM_X4T(R0,R1,R2,R3,ADDR)                                             \
    asm volatile("ldmatrix.sync.aligned.m8n8.x4.trans.shared.b16 {%0,%1,%2,%3}, [%4];" \
        : "=r"(R0), "=r"(R1), "=r"(R2), "=r"(R3) : "r"(ADDR))

#define CP_ASYNC16(SMEM, GPTR) \
    asm volatile("cp.async.cg.shared.global [%0], [%1], 16;" :: "r"(SMEM), "l"(GPTR) : "memory")
#define CP_COMMIT() asm volatile("cp.async.commit_group;" ::: "memory")
#define CP_WAIT1()  asm volatile("cp.async.wait_group 1;" ::: "memory")

// ---------------- RoPE tables (fp64 angle, fp32 trig after reduction) ---------
__global__ void rope_table_kernel() {
    int t = blockIdx.x * 2 + (threadIdx.x >> 6);
    int j = threadIdx.x & 63;  // 0..63
    double inv = exp(-(double)j * (13.815510557964274 / 64.0)); // theta=1e6
    double ang = (double)t * inv;
    const double TWO_PI = 6.283185307179586476925286766559;
    double red = ang - TWO_PI * floor(ang * (1.0 / TWO_PI));
    float c, s;
    sincosf((float)red, &s, &c);
    g_cos[t * 64 + j] = c;
    g_sin[t * 64 + j] = s;
}

// ---------------- merged prep: x->fp16 + 4 weight transposes ------------------
#define PREP_BLOCKS 20480
__global__ __launch_bounds__(256) void prep_kernel(
    const float* __restrict__ x,
    const float* __restrict__ Wq, const float* __restrict__ Wk,
    const float* __restrict__ Wv, const float* __restrict__ Wo,
    __half* __restrict__ xh, __half* __restrict__ wqkv, __half* __restrict__ wo)
{
    __shared__ float t[32][33];
    int bid = blockIdx.x;
    int tid = threadIdx.x;

    if (bid < 8192) {
        size_t i = ((size_t)bid * 256 + tid) * 4;
        float4 v = *(const float4*)(x + i);
        *(__half2*)(xh + i)     = __floats2half2_rn(v.x, v.y);
        *(__half2*)(xh + i + 2) = __floats2half2_rn(v.z, v.w);
        return;
    }
    bid -= 8192;

    const float* W; __half* Wt; int N_;
    if (bid < 4096)      { W = Wq; Wt = wqkv;                        N_ = 2048; }
    else if (bid < 6144) { bid -= 4096; W = Wk; Wt = wqkv + (size_t)2048 * 2048; N_ = 1024; }
    else if (bid < 8192) { bid -= 6144; W = Wv; Wt = wqkv + (size_t)3072 * 2048; N_ = 1024; }
    else                 { bid -= 8192; W = Wo; Wt = wo;             N_ = 2048; }

    const int K = 2048;
    int tilesX = N_ / 32;
    int n0 = (bid % tilesX) * 32, k0 = (bid / tilesX) * 32;
    int tx = tid & 31, ty = tid >> 5;   // 32 x 8
    #pragma unroll
    for (int i = 0; i < 32; i += 8)
        t[ty + i][tx] = W[(size_t)(k0 + ty + i) * N_ + n0 + tx];
    __syncthreads();
    #pragma unroll
    for (int i = 0; i < 32; i += 8)
        Wt[(size_t)(n0 + ty + i) * K + k0 + tx] = __float2half(t[tx][ty + i]);
}

// ---------------- fp16 tensor-core GEMM: C[M,N] = A[M,K] @ B[N,K]^T -----------
// BK=32, 3-stage cp.async smem pipeline, ldmatrix fragment loads.
#define GAS 40   // smem row stride in halves (80B = 5x16B, odd -> ldmatrix clean)
#define GSTG (128 * GAS)                 // halves per tile per stage
#define GEMM_SMEM (3 * 2 * GSTG * 2)     // bytes: 3 stages x (A+B) x 2B = 61440
__global__ __launch_bounds__(256, 2) void gemm_fp16_kernel(
    const __half* __restrict__ A, const __half* __restrict__ Bm,
    float* __restrict__ C, int M, int N_, int K)
{
    extern __shared__ __half sm3[];
    __half* As = sm3;                    // 3 stages, GSTG halves each
    __half* Bs = sm3 + 3 * GSTG;

    int tid = threadIdx.x;
    int wid = tid >> 5, lane = tid & 31;
    int g = lane >> 2, tg = lane & 3;
    int lr = lane & 7;
    int lm = (lane >> 3) & 1;
    int lh = lane >> 4;
    int sel = lane >> 3;
    int warpRow = wid >> 1, warpCol = wid & 1;  // 4 x 2 warps
    int brow = blockIdx.y * 128, bcol = blockIdx.x * 128;

    int rowL[2], segL[2];
    #pragma unroll
    for (int it = 0; it < 2; ++it) {
        int idx = it * 256 + tid;
        rowL[it] = idx >> 2;
        segL[it] = (idx & 3) * 8;
    }
    const __half* ApL[2];
    const __half* BpL[2];
    #pragma unroll
    for (int it = 0; it < 2; ++it) {
        ApL[it] = A  + (size_t)(brow + rowL[it]) * K + segL[it];
        BpL[it] = Bm + (size_t)(bcol + rowL[it]) * K + segL[it];
    }

    uint32_t sA = smem_u32(As), sB = smem_u32(Bs);
    uint32_t cpA[2], cpB[2];
    #pragma unroll
    for (int it = 0; it < 2; ++it) {
        cpA[it] = sA + (uint32_t)((rowL[it] * GAS + segL[it]) * 2);
        cpB[it] = sB + (uint32_t)((rowL[it] * GAS + segL[it]) * 2);
    }
    const uint32_t STGB = GSTG * 2;      // stage stride in bytes

    float acc[2][8][4];
    #pragma unroll
    for (int mi = 0; mi < 2; mi++)
        #pragma unroll
        for (int ni = 0; ni < 8; ni++)
            #pragma unroll
            for (int c = 0; c < 4; c++) acc[mi][ni][c] = 0.f;

    // prologue: stages 0, 1 in flight
    #pragma unroll
    for (int st = 0; st < 2; ++st) {
        #pragma unroll
        for (int it = 0; it < 2; ++it) {
            CP_ASYNC16(cpA[it] + st * STGB, ApL[it] + st * 32);
            CP_ASYNC16(cpB[it] + st * STGB, BpL[it] + st * 32);
        }
        CP_COMMIT();
    }

    const int NK = K / 32;
    int st = 0;                           // stage of current iteration
    for (int itn = 0; itn < NK; ++itn) {
        CP_WAIT1();                       // stage itn complete
        __syncthreads();                  // prior iteration's readers done

        // issue stage itn+2 into buffer (st+2)%3 — flies under the mma below
        if (itn + 2 < NK) {
            int stw = st + 2; if (stw >= 3) stw -= 3;
            int k0 = (itn + 2) * 32;
            #pragma unroll
            for (int it = 0; it < 2; ++it) {
                CP_ASYNC16(cpA[it] + stw * STGB, ApL[it] + k0);
                CP_ASYNC16(cpB[it] + stw * STGB, BpL[it] + k0);
            }
        }
        CP_COMMIT();

        uint32_t bA = sA + st * STGB;
        uint32_t bB = sB + st * STGB;
        #pragma unroll
        for (int ks = 0; ks < 2; ++ks) {
            int kk = ks * 16;
            uint32_t af[2][4];
            #pragma unroll
            for (int mi = 0; mi < 2; mi++) {
                uint32_t addr = bA + (uint32_t)(((warpRow * 32 + mi * 16 + lr + lm * 8) * GAS
                                                 + kk + lh * 8) * 2);
                LDSM_X4(af[mi][0], af[mi][1], af[mi][2], af[mi][3], addr);
            }
            uint32_t bf[8][2];
            #pragma unroll
            for (int nb = 0; nb < 4; nb++) {
                int n0 = warpCol * 64 + nb * 16;
                uint32_t addr = bB + (uint32_t)(((n0 + lr + (sel >> 1) * 8) * GAS
                                                 + kk + (sel & 1) * 8) * 2);
                LDSM_X4(bf[2 * nb][0], bf[2 * nb][1], bf[2 * nb + 1][0], bf[2 * nb + 1][1], addr);
            }
            #pragma unroll
            for (int mi = 0; mi < 2; mi++)
                #pragma unroll
                for (int ni = 0; ni < 8; ni++)
                    mma_f16(acc[mi][ni], af[mi], bf[ni][0], bf[ni][1]);
        }

        if (++st >= 3) st = 0;
    }

    __syncthreads();
    #pragma unroll
    for (int mi = 0; mi < 2; mi++) {
        int r0 = brow + warpRow * 32 + mi * 16 + g;
        #pragma unroll
        for (int ni = 0; ni < 8; ni++) {
            int cn = bcol + warpCol * 64 + ni * 8 + tg * 2;
            *(float2*)(C + (size_t)r0 * N_ + cn) = make_float2(acc[mi][ni][0], acc[mi][ni][1]);
            *(float2*)(C + (size_t)(r0 + 8) * N_ + cn) = make_float2(acc[mi][ni][2], acc[mi][ni][3]);
        }
    }
}

// ------------- merged RMSNorm+RoPE (Q,K) + V convert, warp-per-row ------------
#define NORMV_ROWS (BB * TT * (NH + 2 * NKV))    // 131072
__global__ __launch_bounds__(256) void normv_kernel(
    const float* __restrict__ qkvraw,
    __half* __restrict__ qt, __half* __restrict__ kt, __half* __restrict__ vt,
    const float* __restrict__ qnw, const float* __restrict__ knw)
{
    int r = blockIdx.x * 8 + (threadIdx.x >> 5);
    int lane = threadIdx.x & 31;

    const float* src; __half* dst; const float* w; int nheads; bool donorm;
    if (r < BB * TT * NH) {
        src = qkvraw;            dst = qt; w = qnw; nheads = NH;  donorm = true;
    } else if (r < BB * TT * (NH + NKV)) {
        r -= BB * TT * NH;
        src = qkvraw + 2048;     dst = kt; w = knw; nheads = NKV; donorm = true;
    } else {
        r -= BB * TT * (NH + NKV);
        src = qkvraw + 3072;     dst = vt; w = qnw; nheads = NKV; donorm = false;
    }

    int h  = r % nheads;
    int bt = r / nheads;
    int t  = bt % TT;
    int b  = bt / TT;

    int d0 = lane * 4;
    float4 v = *(const float4*)(src + (size_t)bt * 4096 + h * HD + d0);
    __half* outp = dst + ((size_t)(b * nheads + h) * TT + t) * HD + d0;

    if (!donorm) {
        union { __half2 h2[2]; uint2 u; } pk;
        pk.h2[0] = __floats2half2_rn(v.x, v.y);
        pk.h2[1] = __floats2half2_rn(v.z, v.w);
        *(uint2*)outp = pk.u;
        return;
    }

    float ssq = v.x * v.x + v.y * v.y + v.z * v.z + v.w * v.w;
    #pragma unroll
    for (int off = 16; off; off >>= 1)
        ssq += __shfl_xor_sync(0xffffffffu, ssq, off);
    float rinv = rsqrtf(ssq * (1.0f / HD) + 1e-6f);

    float4 wv = *(const float4*)(w + d0);
    float n0 = v.x * rinv * wv.x;
    float n1 = v.y * rinv * wv.y;
    float n2 = v.z * rinv * wv.z;
    float n3 = v.w * rinv * wv.w;

    float p0 = __shfl_xor_sync(0xffffffffu, n0, 16);
    float p1 = __shfl_xor_sync(0xffffffffu, n1, 16);
    float p2 = __shfl_xor_sync(0xffffffffu, n2, 16);
    float p3 = __shfl_xor_sync(0xffffffffu, n3, 16);

    float sgn = (lane >= 16) ? 1.f : -1.f;
    int j0 = (lane & 15) * 4;
    float4 cc = *(const float4*)(g_cos + t * 64 + j0);
    float4 sc = *(const float4*)(g_sin + t * 64 + j0);

    float o0 = n0 * cc.x + sgn * p0 * sc.x;
    float o1 = n1 * cc.y + sgn * p1 * sc.y;
    float o2 = n2 * cc.z + sgn * p2 * sc.z;
    float o3 = n3 * cc.w + sgn * p3 * sc.w;

    union { __half2 h2[2]; uint2 u; } pk;
    pk.h2[0] = __floats2half2_rn(o0, o1);
    pk.h2[1] = __floats2half2_rn(o2, o3);
    *(uint2*)outp = pk.u;
}

// ------------- Causal flash attention: fp16 mma, double-buffered cp.async -----
// 512 triangular CTAs, LPT order (largest qb first). 2 GQA heads per CTA.
// K and V tiles double-buffered: prefetch issued right after the pre-phase
// barrier; only 2 __syncthreads per kb iteration.
#define US_STR 136   // halves; 272B rows -> ldmatrix conflict-free
#define PS_STR 72
#define FL_KV  (64 * US_STR)
#define FL_U   (128 * US_STR)
#define FLASH_SMEM ((4 * FL_KV + FL_U) * 2)
#define KVB (FL_KV * 2)          // K/V stage stride in bytes
#define NQB    (TT / 64)         // 32 q-blocks

__global__ __launch_bounds__(256) void flash_fp16_kernel(
    const __half* __restrict__ Q, const __half* __restrict__ Kt,
    const __half* __restrict__ Vt, __half* __restrict__ ctx)
{
    extern __shared__ __half smh[];
    __half* Ks = smh;                 // 2 stages
    __half* Vs = smh + 2 * FL_KV;     // 2 stages
    __half* Us = smh + 4 * FL_KV;
    __half* Ps = Us;

    int tid = threadIdx.x;
    int wid = tid >> 5, lane = tid & 31;
    int g = lane >> 2, tg = lane & 3;
    int lr = lane & 7;
    int lm = (lane >> 3) & 1;
    int lh = lane >> 4;
    int p8 = (lane >> 3) & 1;
    int p16 = lane >> 4;

    int hw = wid >> 2;
    int w4 = wid & 3;
    int base = w4 * 16;

    // LPT mapping: largest q-blocks first
    int bid = blockIdx.x;
    int qb = NQB - 1 - (bid >> 4);    // 31 down to 0
    int bk = bid & 15;                // 0..(BB*NKV-1)
    int b = bk / NKV, kvh = bk % NKV;
    int h = kvh * 2 + hw;

    const __half* Kbase = Kt + ((size_t)(b * NKV + kvh) * TT) * HD;
    const __half* Vbase = Vt + ((size_t)(b * NKV + kvh) * TT) * HD;

    uint32_t sK = smem_u32(Ks), sV = smem_u32(Vs), sU = smem_u32(Us), sP = sU;

    int cprow[4], cpc8[4];
    uint32_t cpK[4], cpV[4];
    #pragma unroll
    for (int it = 0; it < 4; ++it) {
        int idx = it * 256 + tid;
        cprow[it] = idx >> 4;
        cpc8[it]  = (idx & 15) * 8;
        cpK[it] = sK + (uint32_t)((cprow[it] * US_STR + cpc8[it]) * 2);
        cpV[it] = sV + (uint32_t)((cprow[it] * US_STR + cpc8[it]) * 2);
    }

    // prefetch K0, V0 into stage 0 (overlaps Q staging)
    #pragma unroll
    for (int it = 0; it < 4; ++it)
        CP_ASYNC16(cpK[it], Kbase + (size_t)cprow[it] * HD + cpc8[it]);
    CP_COMMIT();
    #pragma unroll
    for (int it = 0; it < 4; ++it)
        CP_ASYNC16(cpV[it], Vbase + (size_t)cprow[it] * HD + cpc8[it]);
    CP_COMMIT();

    // stage Q
    {
        const __half* Qh = Q + ((size_t)(b * NH + kvh * 2 + hw) * TT + qb * 64) * HD;
        int t128 = tid & 127;
        #pragma unroll
        for (int it = 0; it < 8; ++it) {
            int idx = it * 128 + t128;
            int r = idx >> 4;
            int c8 = (idx & 15) * 8;
            *(int4*)&Us[(hw * 64 + r) * US_STR + c8] =
                *(const int4*)(Qh + (size_t)r * HD + c8);
        }
    }
    __syncthreads();

    uint32_t qa[8][4];
    #pragma unroll
    for (int ks = 0; ks < 8; ++ks) {
        uint32_t au = sU + (uint32_t)(((hw * 64 + base + lr + lm * 8) * US_STR + ks * 16 + lh * 8) * 2);
        LDSM_X4(qa[ks][0], qa[ks][1], qa[ks][2], qa[ks][3], au);
    }

    float o[16][4];
    #pragma unroll
    for (int ni = 0; ni < 16; ni++)
        #pragma unroll
        for (int c = 0; c < 4; c++) o[ni][c] = 0.f;
    float mrow[2] = {-1e30f, -1e30f};
    float lrow[2] = {0.f, 0.f};

    const float scale = 0.08838834764831845f;   // 128^-0.5
    const float L2E = 1.44269504088896f;

    for (int kb = 0; kb <= qb; ++kb) {
        bool more = (kb < qb);
        int cur = kb & 1, nxt = cur ^ 1;

        CP_WAIT1();          // K(kb) complete
        __syncthreads();     // all warps here: K stage nxt free, K(kb) visible

        // prefetch K(kb+1) into the other stage — flies under S-phase
        if (more) {
            const __half* Kn = Kbase + (size_t)(kb + 1) * 64 * HD;
            #pragma unroll
            for (int it = 0; it < 4; ++it)
                CP_ASYNC16(cpK[it] + nxt * KVB, Kn + (size_t)cprow[it] * HD + cpc8[it]);
        }
        CP_COMMIT();

        // ---- S = Q @ K^T ----------------------------------------------------
        float s[8][4];
        #pragma unroll
        for (int ni = 0; ni < 8; ni++)
            #pragma unroll
            for (int c = 0; c < 4; c++) s[ni][c] = 0.f;

        uint32_t sKc = sK + cur * KVB;
        #pragma unroll
        for (int ks = 0; ks < 8; ++ks) {
            int kk = ks * 16;
            #pragma unroll
            for (int np = 0; np < 4; np++) {
                uint32_t r0, r1, r2, r3;
                uint32_t ak = sKc + (uint32_t)(((np * 16 + p16 * 8 + lr) * US_STR
                                                + kk + p8 * 8) * 2);
                LDSM_X4(r0, r1, r2, r3, ak);
                mma_f16(s[2 * np],     qa[ks], r0, r1);
                mma_f16(s[2 * np + 1], qa[ks], r2, r3);
            }
        }

        // ---- online softmax (ex2.approx) ------------------------------------
        bool diag = (kb == qb);
        int rowA = base + g;
        int rowB = rowA + 8;
        float mA = -1e30f, mB = -1e30f;
        #pragma unroll
        for (int ni = 0; ni < 8; ni++) {
            #pragma unroll
            for (int c = 0; c < 4; c++) {
                float sv = s[ni][c] * scale;
                if (diag) {
                    int kcol = ni * 8 + tg * 2 + (c & 1);
                    int qrow = (c < 2) ? rowA : rowB;
                    if (kcol > qrow) sv = -1e30f;
                }
                s[ni][c] = sv;
            }
            mA = fmaxf(mA, fmaxf(s[ni][0], s[ni][1]));
            mB = fmaxf(mB, fmaxf(s[ni][2], s[ni][3]));
        }
        #pragma unroll
        for (int off = 1; off < 4; off <<= 1) {
            mA = fmaxf(mA, __shfl_xor_sync(0xffffffffu, mA, off));
            mB = fmaxf(mB, __shfl_xor_sync(0xffffffffu, mB, off));
        }
        float mnA = fmaxf(mrow[0], mA);
        float mnB = fmaxf(mrow[1], mB);
        float alA = ex2((mrow[0] - mnA) * L2E);
        float alB = ex2((mrow[1] - mnB) * L2E);
        mrow[0] = mnA; mrow[1] = mnB;

        float lA = 0.f, lB = 0.f;
        #pragma unroll
        for (int ni = 0; ni < 8; ni++) {
            s[ni][0] = ex2((s[ni][0] - mnA) * L2E);
            s[ni][1] = ex2((s[ni][1] - mnA) * L2E);
            s[ni][2] = ex2((s[ni][2] - mnB) * L2E);
            s[ni][3] = ex2((s[ni][3] - mnB) * L2E);
            lA += s[ni][0] + s[ni][1];
            lB += s[ni][2] + s[ni][3];
        }
        #pragma unroll
        for (int off = 1; off < 4; off <<= 1) {
            lA += __shfl_xor_sync(0xffffffffu, lA, off);
            lB += __shfl_xor_sync(0xffffffffu, lB, off);
        }
        lrow[0] = lrow[0] * alA + lA;
        lrow[1] = lrow[1] * alB + lB;
        #pragma unroll
        for (int ni = 0; ni < 16; ni++) {
            o[ni][0] *= alA; o[ni][1] *= alA;
            o[ni][2] *= alB; o[ni][3] *= alB;
        }

        int prowA = hw * 64 + rowA;
        int prowB = hw * 64 + rowB;
        #pragma unroll
        for (int ni = 0; ni < 8; ni++) {
            int cn = ni * 8 + tg * 2;
            *(__half2*)&Ps[prowA * PS_STR + cn] = __floats2half2_rn(s[ni][0], s[ni][1]);
            *(__half2*)&Ps[prowB * PS_STR + cn] = __floats2half2_rn(s[ni][2], s[ni][3]);
        }
        __syncwarp();

        CP_WAIT1();          // V(kb) complete
        __syncthreads();     // all warps past S-phase: V stage nxt free

        // prefetch V(kb+1) — flies under PV
        if (more) {
            const __half* Vn = Vbase + (size_t)(kb + 1) * 64 * HD;
            #pragma unroll
            for (int it = 0; it < 4; ++it)
                CP_ASYNC16(cpV[it] + nxt * KVB, Vn + (size_t)cprow[it] * HD + cpc8[it]);
        }
        CP_COMMIT();

        // ---- O += P @ V -----------------------------------------------------
        uint32_t sVc = sV + cur * KVB;
        #pragma unroll
        for (int ks = 0; ks < 4; ++ks) {
            int kk = ks * 16;
            uint32_t pa4[4];
            uint32_t ap = sP + (uint32_t)(((hw * 64 + base + lr + lm * 8) * PS_STR + kk + lh * 8) * 2);
            LDSM_X4(pa4[0], pa4[1], pa4[2], pa4[3], ap);
            #pragma unroll
            for (int np = 0; np < 8; np++) {
                uint32_t r0, r1, r2, r3;
                uint32_t av = sVc + (uint32_t)(((kk + p8 * 8 + lr) * US_STR
                                                + np * 16 + p16 * 8) * 2);
                LDSM_X4T(r0, r1, r2, r3, av);
                mma_f16(o[2 * np],     pa4, r0, r1);
                mma_f16(o[2 * np + 1], pa4, r2, r3);
            }
        }
    }

    float ivA = 1.0f / lrow[0];
    float ivB = 1.0f / lrow[1];
    int qA = qb * 64 + base + g;
    int qB = qA + 8;
    size_t offA = (size_t)(b * TT + qA) * (NH * HD) + h * HD;
    size_t offB = (size_t)(b * TT + qB) * (NH * HD) + h * HD;
    #pragma unroll
    for (int ni = 0; ni < 16; ni++) {
        int dn = ni * 8 + tg * 2;
        *(__half2*)(ctx + offA + dn) = __floats2half2_rn(o[ni][0] * ivA, o[ni][1] * ivA);
        *(__half2*)(ctx + offB + dn) = __floats2half2_rn(o[ni][2] * ivB, o[ni][3] * ivB);
    }
}

// ---------------------------- launch -----------------------------------------
extern "C" void kernel_launch(void* const* d_in, const int* in_sizes, int n_in,
                              void* d_out, int out_size)
{
    const float* x    = (const float*)d_in[0];
    // d_in[1] = attn_mask (pure causal; applied analytically)
    const float* Wq   = (const float*)d_in[2];
    const float* Wk   = (const float*)d_in[3];
    const float* Wv   = (const float*)d_in[4];
    const float* Wo   = (const float*)d_in[5];
    const float* qnw  = (const float*)d_in[6];
    const float* knw  = (const float*)d_in[7];
    float* out = (float*)d_out;

    float *qkvraw;
    __half *qt, *kt, *vt, *xh, *wqkv, *wo, *ctx;
    cudaGetSymbolAddress((void**)&qkvraw, g_qkvraw);
    cudaGetSymbolAddress((void**)&qt,   g_qt);
    cudaGetSymbolAddress((void**)&kt,   g_kt);
    cudaGetSymbolAddress((void**)&vt,   g_vt);
    cudaGetSymbolAddress((void**)&xh,   g_xh);
    cudaGetSymbolAddress((void**)&wqkv, g_wqkv);
    cudaGetSymbolAddress((void**)&wo,   g_wo);
    cudaGetSymbolAddress((void**)&ctx,  g_ctx);

    cudaFuncSetAttribute(flash_fp16_kernel, cudaFuncAttributeMaxDynamicSharedMemorySize,
                         FLASH_SMEM);
    cudaFuncSetAttribute(gemm_fp16_kernel, cudaFuncAttributeMaxDynamicSharedMemorySize,
                         GEMM_SMEM);

    // 0: rope table
    rope_table_kernel<<<TT / 2, 128>>>();
    // 1: merged prep (x->fp16, Wq/Wk/Wv/Wo transposed fp16)
    prep_kernel<<<PREP_BLOCKS, 256>>>(x, Wq, Wk, Wv, Wo, xh, wqkv, wo);
    // 2: fused QKV projection (N=4096, 3-stage cp.async)
    gemm_fp16_kernel<<<dim3(4096 / 128, MM / 128), 256, GEMM_SMEM>>>(
        xh, wqkv, qkvraw, MM, 4096, HH);
    // 3: merged RMSNorm/RoPE (Q,K) + V convert, warp-per-row
    normv_kernel<<<NORMV_ROWS / 8, 256>>>(qkvraw, qt, kt, vt, qnw, knw);
    // 4: flash attention (LPT order, double-buffered K/V, ex2.approx)
    flash_fp16_kernel<<<NQB * BB * NKV, 256, FLASH_SMEM>>>(qt, kt, vt, ctx);
    // 5: output projection
    gemm_fp16_kernel<<<dim3(2048 / 128, MM / 128), 256, GEMM_SMEM>>>(
        ctx, wo, out, MM, 2048, HH);
}

// round 17
// speedup vs baseline: 1.0022x; 1.0022x over previous
#include <cuda_runtime.h>
#include <cuda_fp16.h>
#include <cstdint>
#include <cstddef>
#include <math.h>

// Problem constants
#define BB   2
#define TT   2048
#define HH   2048
#define NH   16
#define NKV  8
#define HD   128
#define MM   (BB*TT)            // 4096 rows

// ---------------- scratch (static device globals; no allocation) -------------
__device__ __half g_qkvh[(size_t)MM * 4096];       // [b*T+t, {Q|K|V}] fp16
__device__ __half g_qt[(size_t)BB * NH * TT * HD]; // [b,h,t,d] fp16
__device__ __half g_kt[(size_t)BB * NKV * TT * HD];
__device__ __half g_vt[(size_t)BB * NKV * TT * HD];
__device__ __half g_xh[(size_t)MM * HH];           // x fp16
__device__ __half g_wqkv[(size_t)4096 * 2048];     // [N=4096, K=2048] fp16 (Q|K|V rows)
__device__ __half g_wo[(size_t)2048 * 2048];       // Wo^T [N,K] fp16
__device__ __half g_ctx[(size_t)MM * HH];          // [b*T+t, h*HD+d] fp16
__device__ float g_cos[TT * 64];
__device__ float g_sin[TT * 64];

// ---------------- helpers ----------------------------------------------------
__device__ __forceinline__ uint32_t smem_u32(const void* p) {
    uint32_t a;
    asm("{ .reg .u64 t; cvta.to.shared.u64 t, %1; cvt.u32.u64 %0, t; }" : "=r"(a) : "l"(p));
    return a;
}

__device__ __forceinline__ void mma_f16(float c[4], const uint32_t a[4],
                                        uint32_t b0, uint32_t b1) {
    asm volatile(
        "mma.sync.aligned.m16n8k16.row.col.f32.f16.f16.f32 "
        "{%0,%1,%2,%3}, {%4,%5,%6,%7}, {%8,%9}, {%0,%1,%2,%3};\n"
        : "+f"(c[0]), "+f"(c[1]), "+f"(c[2]), "+f"(c[3])
        : "r"(a[0]), "r"(a[1]), "r"(a[2]), "r"(a[3]), "r"(b0), "r"(b1));
}

#define LDSM_X4(R0,R1,R2,R3,ADDR)                                              \
    asm volatile("ldmatrix.sync.aligned.m8n8.x4.shared.b16 {%0,%1,%2,%3}, [%4];" \
        : "=r"(R0), "=r"(R1), "=r"(R2), "=r"(R3) : "r"(ADDR))
#define LDSM_X4T(R0,R1,R2,R3,ADDR)                                             \
    asm volatile("ldmatrix.sync.aligned.m8n8.x4.trans.shared.b16 {%0,%1,%2,%3}, [%4];" \
        : "=r"(R0), "=r"(R1), "=r"(R2), "=r"(R3) : "r"(ADDR))

#define CP_ASYNC16(SMEM, GPTR) \
    asm volatile("cp.async.cg.shared.global [%0], [%1], 16;" :: "r"(SMEM), "l"(GPTR) : "memory")
#define CP_COMMIT() asm volatile("cp.async.commit_group;" ::: "memory")
#define CP_WAIT1()  asm volatile("cp.async.wait_group 1;" ::: "memory")

// ---------------- merged prep: rope tables + x->fp16 + 4 weight transposes ----
// blocks [0, 8192)        : conv x
// blocks [8192, 16384)    : W transposes (Wq 4096 | Wk 2048 | Wv 2048)
// blocks [16384, 20480)   : Wo transpose
// blocks [20480, 20992)   : rope tables (4 t-values per block)
#define PREP_BLOCKS 20992
__global__ __launch_bounds__(256) void prep_kernel(
    const float* __restrict__ x,
    const float* __restrict__ Wq, const float* __restrict__ Wk,
    const float* __restrict__ Wv, const float* __restrict__ Wo,
    __half* __restrict__ xh, __half* __restrict__ wqkv, __half* __restrict__ wo)
{
    __shared__ float t[32][33];
    int bid = blockIdx.x;
    int tid = threadIdx.x;

    if (bid < 8192) {
        size_t i = ((size_t)bid * 256 + tid) * 4;
        float4 v = *(const float4*)(x + i);
        *(__half2*)(xh + i)     = __floats2half2_rn(v.x, v.y);
        *(__half2*)(xh + i + 2) = __floats2half2_rn(v.z, v.w);
        return;
    }
    if (bid >= 20480) {
        // rope tables (fp64 angle, fp32 trig after range reduction)
        int tt = (bid - 20480) * 4 + (tid >> 6);
        int j  = tid & 63;
        double inv = exp(-(double)j * (13.815510557964274 / 64.0)); // theta=1e6
        double ang = (double)tt * inv;
        const double TWO_PI = 6.283185307179586476925286766559;
        double red = ang - TWO_PI * floor(ang * (1.0 / TWO_PI));
        float c, s;
        sincosf((float)red, &s, &c);
        g_cos[tt * 64 + j] = c;
        g_sin[tt * 64 + j] = s;
        return;
    }
    bid -= 8192;

    const float* W; __half* Wt; int N_;
    if (bid < 4096)      { W = Wq; Wt = wqkv;                        N_ = 2048; }
    else if (bid < 6144) { bid -= 4096; W = Wk; Wt = wqkv + (size_t)2048 * 2048; N_ = 1024; }
    else if (bid < 8192) { bid -= 6144; W = Wv; Wt = wqkv + (size_t)3072 * 2048; N_ = 1024; }
    else                 { bid -= 8192; W = Wo; Wt = wo;             N_ = 2048; }

    const int K = 2048;
    int tilesX = N_ / 32;
    int n0 = (bid % tilesX) * 32, k0 = (bid / tilesX) * 32;
    int tx = tid & 31, ty = tid >> 5;   // 32 x 8
    #pragma unroll
    for (int i = 0; i < 32; i += 8)
        t[ty + i][tx] = W[(size_t)(k0 + ty + i) * N_ + n0 + tx];
    __syncthreads();
    #pragma unroll
    for (int i = 0; i < 32; i += 8)
        Wt[(size_t)(n0 + ty + i) * K + k0 + tx] = __float2half(t[tx][ty + i]);
}

// ---------------- fp16 tensor-core GEMM: C[M,N] = A[M,K] @ B[N,K]^T -----------
// BK=32, 3-stage cp.async smem pipeline, ldmatrix fragment loads.
// HALFOUT selects fp16 vs fp32 output.
#define GAS 40   // smem row stride in halves (80B = 5x16B, odd -> ldmatrix clean)
#define GSTG (128 * GAS)                 // halves per tile per stage
#define GEMM_SMEM (3 * 2 * GSTG * 2)     // bytes: 3 stages x (A+B) x 2B = 61440
template <bool HALFOUT>
__global__ __launch_bounds__(256, 2) void gemm_fp16_kernel(
    const __half* __restrict__ A, const __half* __restrict__ Bm,
    void* __restrict__ Cv, int M, int N_, int K)
{
    extern __shared__ __half sm3[];
    __half* As = sm3;                    // 3 stages, GSTG halves each
    __half* Bs = sm3 + 3 * GSTG;

    int tid = threadIdx.x;
    int wid = tid >> 5, lane = tid & 31;
    int g = lane >> 2, tg = lane & 3;
    int lr = lane & 7;
    int lm = (lane >> 3) & 1;
    int lh = lane >> 4;
    int sel = lane >> 3;
    int warpRow = wid >> 1, warpCol = wid & 1;  // 4 x 2 warps
    int brow = blockIdx.y * 128, bcol = blockIdx.x * 128;

    int rowL[2], segL[2];
    #pragma unroll
    for (int it = 0; it < 2; ++it) {
        int idx = it * 256 + tid;
        rowL[it] = idx >> 2;
        segL[it] = (idx & 3) * 8;
    }
    const __half* ApL[2];
    const __half* BpL[2];
    #pragma unroll
    for (int it = 0; it < 2; ++it) {
        ApL[it] = A  + (size_t)(brow + rowL[it]) * K + segL[it];
        BpL[it] = Bm + (size_t)(bcol + rowL[it]) * K + segL[it];
    }

    uint32_t sA = smem_u32(As), sB = smem_u32(Bs);
    uint32_t cpA[2], cpB[2];
    #pragma unroll
    for (int it = 0; it < 2; ++it) {
        cpA[it] = sA + (uint32_t)((rowL[it] * GAS + segL[it]) * 2);
        cpB[it] = sB + (uint32_t)((rowL[it] * GAS + segL[it]) * 2);
    }
    const uint32_t STGB = GSTG * 2;      // stage stride in bytes

    float acc[2][8][4];
    #pragma unroll
    for (int mi = 0; mi < 2; mi++)
        #pragma unroll
        for (int ni = 0; ni < 8; ni++)
            #pragma unroll
            for (int c = 0; c < 4; c++) acc[mi][ni][c] = 0.f;

    // prologue: stages 0, 1 in flight
    #pragma unroll
    for (int st = 0; st < 2; ++st) {
        #pragma unroll
        for (int it = 0; it < 2; ++it) {
            CP_ASYNC16(cpA[it] + st * STGB, ApL[it] + st * 32);
            CP_ASYNC16(cpB[it] + st * STGB, BpL[it] + st * 32);
        }
        CP_COMMIT();
    }

    const int NK = K / 32;
    int st = 0;                           // stage of current iteration
    for (int itn = 0; itn < NK; ++itn) {
        CP_WAIT1();                       // stage itn complete
        __syncthreads();                  // prior iteration's readers done

        // issue stage itn+2 into buffer (st+2)%3 — flies under the mma below
        if (itn + 2 < NK) {
            int stw = st + 2; if (stw >= 3) stw -= 3;
            int k0 = (itn + 2) * 32;
            #pragma unroll
            for (int it = 0; it < 2; ++it) {
                CP_ASYNC16(cpA[it] + stw * STGB, ApL[it] + k0);
                CP_ASYNC16(cpB[it] + stw * STGB, BpL[it] + k0);
            }
        }
        CP_COMMIT();

        uint32_t bA = sA + st * STGB;
        uint32_t bB = sB + st * STGB;
        #pragma unroll
        for (int ks = 0; ks < 2; ++ks) {
            int kk = ks * 16;
            uint32_t af[2][4];
            #pragma unroll
            for (int mi = 0; mi < 2; mi++) {
                uint32_t addr = bA + (uint32_t)(((warpRow * 32 + mi * 16 + lr + lm * 8) * GAS
                                                 + kk + lh * 8) * 2);
                LDSM_X4(af[mi][0], af[mi][1], af[mi][2], af[mi][3], addr);
            }
            uint32_t bf[8][2];
            #pragma unroll
            for (int nb = 0; nb < 4; nb++) {
                int n0 = warpCol * 64 + nb * 16;
                uint32_t addr = bB + (uint32_t)(((n0 + lr + (sel >> 1) * 8) * GAS
                                                 + kk + (sel & 1) * 8) * 2);
                LDSM_X4(bf[2 * nb][0], bf[2 * nb][1], bf[2 * nb + 1][0], bf[2 * nb + 1][1], addr);
            }
            #pragma unroll
            for (int mi = 0; mi < 2; mi++)
                #pragma unroll
                for (int ni = 0; ni < 8; ni++)
                    mma_f16(acc[mi][ni], af[mi], bf[ni][0], bf[ni][1]);
        }

        if (++st >= 3) st = 0;
    }

    __syncthreads();
    #pragma unroll
    for (int mi = 0; mi < 2; mi++) {
        int r0 = brow + warpRow * 32 + mi * 16 + g;
        #pragma unroll
        for (int ni = 0; ni < 8; ni++) {
            int cn = bcol + warpCol * 64 + ni * 8 + tg * 2;
            if (HALFOUT) {
                __half* C = (__half*)Cv;
                *(__half2*)(C + (size_t)r0 * N_ + cn) =
                    __floats2half2_rn(acc[mi][ni][0], acc[mi][ni][1]);
                *(__half2*)(C + (size_t)(r0 + 8) * N_ + cn) =
                    __floats2half2_rn(acc[mi][ni][2], acc[mi][ni][3]);
            } else {
                float* C = (float*)Cv;
                *(float2*)(C + (size_t)r0 * N_ + cn) = make_float2(acc[mi][ni][0], acc[mi][ni][1]);
                *(float2*)(C + (size_t)(r0 + 8) * N_ + cn) = make_float2(acc[mi][ni][2], acc[mi][ni][3]);
            }
        }
    }
}

// ------------- merged RMSNorm+RoPE (Q,K) + V copy, warp-per-row (fp16 in) -----
#define NORMV_ROWS (BB * TT * (NH + 2 * NKV))    // 131072
__global__ __launch_bounds__(256) void normv_kernel(
    const __half* __restrict__ qkvh,
    __half* __restrict__ qt, __half* __restrict__ kt, __half* __restrict__ vt,
    const float* __restrict__ qnw, const float* __restrict__ knw)
{
    int r = blockIdx.x * 8 + (threadIdx.x >> 5);
    int lane = threadIdx.x & 31;

    const __half* src; __half* dst; const float* w; int nheads; bool donorm;
    if (r < BB * TT * NH) {
        src = qkvh;            dst = qt; w = qnw; nheads = NH;  donorm = true;
    } else if (r < BB * TT * (NH + NKV)) {
        r -= BB * TT * NH;
        src = qkvh + 2048;     dst = kt; w = knw; nheads = NKV; donorm = true;
    } else {
        r -= BB * TT * (NH + NKV);
        src = qkvh + 3072;     dst = vt; w = qnw; nheads = NKV; donorm = false;
    }

    int h  = r % nheads;
    int bt = r / nheads;
    int t  = bt % TT;
    int b  = bt / TT;

    int d0 = lane * 4;
    uint2 raw = *(const uint2*)(src + (size_t)bt * 4096 + h * HD + d0);
    __half* outp = dst + ((size_t)(b * nheads + h) * TT + t) * HD + d0;

    if (!donorm) {
        *(uint2*)outp = raw;          // V: bit-copy (already fp16)
        return;
    }

    float2 v01 = __half22float2(*(__half2*)&raw.x);
    float2 v23 = __half22float2(*(__half2*)&raw.y);
    float vx = v01.x, vy = v01.y, vz = v23.x, vw = v23.y;

    float ssq = vx * vx + vy * vy + vz * vz + vw * vw;
    #pragma unroll
    for (int off = 16; off; off >>= 1)
        ssq += __shfl_xor_sync(0xffffffffu, ssq, off);
    float rinv = rsqrtf(ssq * (1.0f / HD) + 1e-6f);

    float4 wv = *(const float4*)(w + d0);
    float n0 = vx * rinv * wv.x;
    float n1 = vy * rinv * wv.y;
    float n2 = vz * rinv * wv.z;
    float n3 = vw * rinv * wv.w;

    float p0 = __shfl_xor_sync(0xffffffffu, n0, 16);
    float p1 = __shfl_xor_sync(0xffffffffu, n1, 16);
    float p2 = __shfl_xor_sync(0xffffffffu, n2, 16);
    float p3 = __shfl_xor_sync(0xffffffffu, n3, 16);

    float sgn = (lane >= 16) ? 1.f : -1.f;
    int j0 = (lane & 15) * 4;
    float4 cc = *(const float4*)(g_cos + t * 64 + j0);
    float4 sc = *(const float4*)(g_sin + t * 64 + j0);

    float o0 = n0 * cc.x + sgn * p0 * sc.x;
    float o1 = n1 * cc.y + sgn * p1 * sc.y;
    float o2 = n2 * cc.z + sgn * p2 * sc.z;
    float o3 = n3 * cc.w + sgn * p3 * sc.w;

    union { __half2 h2[2]; uint2 u; } pk;
    pk.h2[0] = __floats2half2_rn(o0, o1);
    pk.h2[1] = __floats2half2_rn(o2, o3);
    *(uint2*)outp = pk.u;
}

// ------------- Causal flash attention: fp16 mma, cp.async pipeline ------------
// 512 triangular CTAs, launched longest-first: bid -> qb = 31 - bid/16 (LPT).
// 2 GQA heads per CTA. (R15 build — best measured.)
#define US_STR 136   // halves; 272B rows -> ldmatrix conflict-free
#define PS_STR 72
#define FL_KV  (64 * US_STR)
#define FL_U   (128 * US_STR)
#define FLASH_SMEM ((2 * FL_KV + FL_U) * 2)
#define NQB    (TT / 64)         // 32 q-blocks

__global__ __launch_bounds__(256) void flash_fp16_kernel(
    const __half* __restrict__ Q, const __half* __restrict__ Kt,
    const __half* __restrict__ Vt, __half* __restrict__ ctx)
{
    extern __shared__ __half smh[];
    __half* Ks = smh;
    __half* Vs = smh + FL_KV;
    __half* Us = smh + 2 * FL_KV;
    __half* Ps = Us;

    int tid = threadIdx.x;
    int wid = tid >> 5, lane = tid & 31;
    int g = lane >> 2, tg = lane & 3;
    int lr = lane & 7;
    int lm = (lane >> 3) & 1;
    int lh = lane >> 4;
    int p8 = (lane >> 3) & 1;
    int p16 = lane >> 4;

    int hw = wid >> 2;
    int w4 = wid & 3;
    int base = w4 * 16;

    // LPT mapping: largest q-blocks first
    int bid = blockIdx.x;
    int qb = NQB - 1 - (bid >> 4);    // 31 down to 0
    int bk = bid & 15;                // 0..(BB*NKV-1)
    int b = bk / NKV, kvh = bk % NKV;
    int h = kvh * 2 + hw;

    const __half* Kbase = Kt + ((size_t)(b * NKV + kvh) * TT) * HD;
    const __half* Vbase = Vt + ((size_t)(b * NKV + kvh) * TT) * HD;

    uint32_t sK = smem_u32(Ks), sV = smem_u32(Vs), sU = smem_u32(Us), sP = sU;

    int cprow[4], cpc8[4];
    uint32_t cpK[4], cpV[4];
    #pragma unroll
    for (int it = 0; it < 4; ++it) {
        int idx = it * 256 + tid;
        cprow[it] = idx >> 4;
        cpc8[it]  = (idx & 15) * 8;
        cpK[it] = sK + (uint32_t)((cprow[it] * US_STR + cpc8[it]) * 2);
        cpV[it] = sV + (uint32_t)((cprow[it] * US_STR + cpc8[it]) * 2);
    }

    // prefetch K0, V0 (overlaps Q staging)
    #pragma unroll
    for (int it = 0; it < 4; ++it)
        CP_ASYNC16(cpK[it], Kbase + (size_t)cprow[it] * HD + cpc8[it]);
    CP_COMMIT();
    #pragma unroll
    for (int it = 0; it < 4; ++it)
        CP_ASYNC16(cpV[it], Vbase + (size_t)cprow[it] * HD + cpc8[it]);
    CP_COMMIT();

    // stage Q
    {
        const __half* Qh = Q + ((size_t)(b * NH + kvh * 2 + hw) * TT + qb * 64) * HD;
        int t128 = tid & 127;
        #pragma unroll
        for (int it = 0; it < 8; ++it) {
            int idx = it * 128 + t128;
            int r = idx >> 4;
            int c8 = (idx & 15) * 8;
            *(int4*)&Us[(hw * 64 + r) * US_STR + c8] =
                *(const int4*)(Qh + (size_t)r * HD + c8);
        }
    }
    __syncthreads();

    uint32_t qa[8][4];
    #pragma unroll
    for (int ks = 0; ks < 8; ++ks) {
        uint32_t au = sU + (uint32_t)(((hw * 64 + base + lr + lm * 8) * US_STR + ks * 16 + lh * 8) * 2);
        LDSM_X4(qa[ks][0], qa[ks][1], qa[ks][2], qa[ks][3], au);
    }

    float o[16][4];
    #pragma unroll
    for (int ni = 0; ni < 16; ni++)
        #pragma unroll
        for (int c = 0; c < 4; c++) o[ni][c] = 0.f;
    float mrow[2] = {-1e30f, -1e30f};
    float lrow[2] = {0.f, 0.f};

    const float scale = 0.08838834764831845f;   // 128^-0.5
    const float L2E = 1.44269504088896f;

    for (int kb = 0; kb <= qb; ++kb) {
        bool more = (kb < qb);
        CP_WAIT1();
        __syncthreads();

        float s[8][4];
        #pragma unroll
        for (int ni = 0; ni < 8; ni++)
            #pragma unroll
            for (int c = 0; c < 4; c++) s[ni][c] = 0.f;

        #pragma unroll
        for (int ks = 0; ks < 8; ++ks) {
            int kk = ks * 16;
            #pragma unroll
            for (int np = 0; np < 4; np++) {
                uint32_t r0, r1, r2, r3;
                uint32_t ak = sK + (uint32_t)(((np * 16 + p16 * 8 + lr) * US_STR
                                               + kk + p8 * 8) * 2);
                LDSM_X4(r0, r1, r2, r3, ak);
                mma_f16(s[2 * np],     qa[ks], r0, r1);
                mma_f16(s[2 * np + 1], qa[ks], r2, r3);
            }
        }
        __syncthreads();

        if (more) {
            const __half* Kn = Kbase + (size_t)(kb + 1) * 64 * HD;
            #pragma unroll
            for (int it = 0; it < 4; ++it)
                CP_ASYNC16(cpK[it], Kn + (size_t)cprow[it] * HD + cpc8[it]);
        }
        CP_COMMIT();

        bool diag = (kb == qb);
        int rowA = base + g;
        int rowB = rowA + 8;
        float mA = -1e30f, mB = -1e30f;
        #pragma unroll
        for (int ni = 0; ni < 8; ni++) {
            #pragma unroll
            for (int c = 0; c < 4; c++) {
                float sv = s[ni][c] * scale;
                if (diag) {
                    int kcol = ni * 8 + tg * 2 + (c & 1);
                    int qrow = (c < 2) ? rowA : rowB;
                    if (kcol > qrow) sv = -1e30f;
                }
                s[ni][c] = sv;
            }
            mA = fmaxf(mA, fmaxf(s[ni][0], s[ni][1]));
            mB = fmaxf(mB, fmaxf(s[ni][2], s[ni][3]));
        }
        #pragma unroll
        for (int off = 1; off < 4; off <<= 1) {
            mA = fmaxf(mA, __shfl_xor_sync(0xffffffffu, mA, off));
            mB = fmaxf(mB, __shfl_xor_sync(0xffffffffu, mB, off));
        }
        float mnA = fmaxf(mrow[0], mA);
        float mnB = fmaxf(mrow[1], mB);
        float alA = exp2f((mrow[0] - mnA) * L2E);
        float alB = exp2f((mrow[1] - mnB) * L2E);
        mrow[0] = mnA; mrow[1] = mnB;

        float lA = 0.f, lB = 0.f;
        #pragma unroll
        for (int ni = 0; ni < 8; ni++) {
            s[ni][0] = exp2f((s[ni][0] - mnA) * L2E);
            s[ni][1] = exp2f((s[ni][1] - mnA) * L2E);
            s[ni][2] = exp2f((s[ni][2] - mnB) * L2E);
            s[ni][3] = exp2f((s[ni][3] - mnB) * L2E);
            lA += s[ni][0] + s[ni][1];
            lB += s[ni][2] + s[ni][3];
        }
        #pragma unroll
        for (int off = 1; off < 4; off <<= 1) {
            lA += __shfl_xor_sync(0xffffffffu, lA, off);
            lB += __shfl_xor_sync(0xffffffffu, lB, off);
        }
        lrow[0] = lrow[0] * alA + lA;
        lrow[1] = lrow[1] * alB + lB;
        #pragma unroll
        for (int ni = 0; ni < 16; ni++) {
            o[ni][0] *= alA; o[ni][1] *= alA;
            o[ni][2] *= alB; o[ni][3] *= alB;
        }

        int prowA = hw * 64 + rowA;
        int prowB = hw * 64 + rowB;
        #pragma unroll
        for (int ni = 0; ni < 8; ni++) {
            int cn = ni * 8 + tg * 2;
            *(__half2*)&Ps[prowA * PS_STR + cn] = __floats2half2_rn(s[ni][0], s[ni][1]);
            *(__half2*)&Ps[prowB * PS_STR + cn] = __floats2half2_rn(s[ni][2], s[ni][3]);
        }
        __syncwarp();

        CP_WAIT1();
        __syncthreads();

        #pragma unroll
        for (int ks = 0; ks < 4; ++ks) {
            int kk = ks * 16;
            uint32_t pa4[4];
            uint32_t ap = sP + (uint32_t)(((hw * 64 + base + lr + lm * 8) * PS_STR + kk + lh * 8) * 2);
            LDSM_X4(pa4[0], pa4[1], pa4[2], pa4[3], ap);
            #pragma unroll
            for (int np = 0; np < 8; np++) {
                uint32_t r0, r1, r2, r3;
                uint32_t av = sV + (uint32_t)(((kk + p8 * 8 + lr) * US_STR
                                               + np * 16 + p16 * 8) * 2);
                LDSM_X4T(r0, r1, r2, r3, av);
                mma_f16(o[2 * np],     pa4, r0, r1);
                mma_f16(o[2 * np + 1], pa4, r2, r3);
            }
        }
        __syncthreads();

        if (more) {
            const __half* Vn = Vbase + (size_t)(kb + 1) * 64 * HD;
            #pragma unroll
            for (int it = 0; it < 4; ++it)
                CP_ASYNC16(cpV[it], Vn + (size_t)cprow[it] * HD + cpc8[it]);
        }
        CP_COMMIT();
    }

    float ivA = 1.0f / lrow[0];
    float ivB = 1.0f / lrow[1];
    int qA = qb * 64 + base + g;
    int qB = qA + 8;
    size_t offA = (size_t)(b * TT + qA) * (NH * HD) + h * HD;
    size_t offB = (size_t)(b * TT + qB) * (NH * HD) + h * HD;
    #pragma unroll
    for (int ni = 0; ni < 16; ni++) {
        int dn = ni * 8 + tg * 2;
        *(__half2*)(ctx + offA + dn) = __floats2half2_rn(o[ni][0] * ivA, o[ni][1] * ivA);
        *(__half2*)(ctx + offB + dn) = __floats2half2_rn(o[ni][2] * ivB, o[ni][3] * ivB);
    }
}

// ---------------------------- launch -----------------------------------------
extern "C" void kernel_launch(void* const* d_in, const int* in_sizes, int n_in,
                              void* d_out, int out_size)
{
    const float* x    = (const float*)d_in[0];
    // d_in[1] = attn_mask (pure causal; applied analytically)
    const float* Wq   = (const float*)d_in[2];
    const float* Wk   = (const float*)d_in[3];
    const float* Wv   = (const float*)d_in[4];
    const float* Wo   = (const float*)d_in[5];
    const float* qnw  = (const float*)d_in[6];
    const float* knw  = (const float*)d_in[7];
    float* out = (float*)d_out;

    __half *qkvh, *qt, *kt, *vt, *xh, *wqkv, *wo, *ctx;
    cudaGetSymbolAddress((void**)&qkvh, g_qkvh);
    cudaGetSymbolAddress((void**)&qt,   g_qt);
    cudaGetSymbolAddress((void**)&kt,   g_kt);
    cudaGetSymbolAddress((void**)&vt,   g_vt);
    cudaGetSymbolAddress((void**)&xh,   g_xh);
    cudaGetSymbolAddress((void**)&wqkv, g_wqkv);
    cudaGetSymbolAddress((void**)&wo,   g_wo);
    cudaGetSymbolAddress((void**)&ctx,  g_ctx);

    cudaFuncSetAttribute(flash_fp16_kernel, cudaFuncAttributeMaxDynamicSharedMemorySize,
                         FLASH_SMEM);
    cudaFuncSetAttribute(gemm_fp16_kernel<true>, cudaFuncAttributeMaxDynamicSharedMemorySize,
                         GEMM_SMEM);
    cudaFuncSetAttribute(gemm_fp16_kernel<false>, cudaFuncAttributeMaxDynamicSharedMemorySize,
                         GEMM_SMEM);

    // 0: merged prep (rope tables, x->fp16, Wq/Wk/Wv/Wo transposed fp16)
    prep_kernel<<<PREP_BLOCKS, 256>>>(x, Wq, Wk, Wv, Wo, xh, wqkv, wo);
    // 1: fused QKV projection (N=4096, 3-stage cp.async, fp16 out)
    gemm_fp16_kernel<true><<<dim3(4096 / 128, MM / 128), 256, GEMM_SMEM>>>(
        xh, wqkv, qkvh, MM, 4096, HH);
    // 2: merged RMSNorm/RoPE (Q,K) + V copy, warp-per-row (fp16 in)
    normv_kernel<<<NORMV_ROWS / 8, 256>>>(qkvh, qt, kt, vt, qnw, knw);
    // 3: flash attention (512 triangular CTAs, LPT order)
    flash_fp16_kernel<<<NQB * BB * NKV, 256, FLASH_SMEM>>>(qt, kt, vt, ctx);
    // 4: output projection (fp32 out)
    gemm_fp16_kernel<false><<<dim3(2048 / 128, MM / 128), 256, GEMM_SMEM>>>(
        ctx, wo, out, MM, 2048, HH);
}